// round 13
// baseline (speedup 1.0000x reference)
#include <cuda_runtime.h>
#include <cuda_fp16.h>
#include <cstdint>

#define NN   50000
#define EE   800000
#define DIN  128
#define DHID 64
#define DOUT 128

// ---------------- scratch (static device globals; no allocation) ----------------
__device__ __align__(16) float g_dinv[NN];
__device__ int   g_cnt[NN];      // zero at load; re-zeroed by fused gemm blocks each call
__device__ int   g_rank[EE];     // per-edge rank within its dst bucket (from k_count)
__device__ int   g_offs[NN];     // block-local exclusive prefix (scan1)
__device__ int   g_part[256];
__device__ int   g_part2[256];   // per-256-block global offset (scan2)
__device__ int   g_csr[EE];
__device__ __align__(16) __half2 g_hs[NN * 32];      // fp16 conv1 pre-agg features
__device__ __align__(16) __half2 g_zs[NN * 32];      // fp16 conv2 pre-agg features
__device__ __align__(16) float   g_agg [NN * DHID];  // gather1 result (fp32)
__device__ __align__(16) float   g_agg2[NN * DHID];  // gather2 result (fp32)

__device__ __forceinline__ uint32_t smem_u32(const void* p) {
    return (uint32_t)__cvta_generic_to_shared(p);
}

#define LDMATRIX_X4(a0,a1,a2,a3,addr) \
    asm volatile("ldmatrix.sync.aligned.m8n8.x4.shared.b16 {%0,%1,%2,%3}, [%4];" \
        : "=r"(a0),"=r"(a1),"=r"(a2),"=r"(a3) : "r"(addr))
#define LDMATRIX_X2T(b0,b1,addr) \
    asm volatile("ldmatrix.sync.aligned.m8n8.x2.trans.shared.b16 {%0,%1}, [%2];" \
        : "=r"(b0),"=r"(b1) : "r"(addr))
#define MMA16816(d0,d1,d2,d3,a0,a1,a2,a3,b0,b1) \
    asm volatile("mma.sync.aligned.m16n8k16.row.col.f32.f16.f16.f32 " \
        "{%0,%1,%2,%3},{%4,%5,%6,%7},{%8,%9},{%0,%1,%2,%3};" \
        : "+f"(d0),"+f"(d1),"+f"(d2),"+f"(d3) \
        : "r"(a0),"r"(a1),"r"(a2),"r"(a3),"r"(b0),"r"(b1))

// ---------------- count: degree histogram + per-edge rank ----------------
__global__ void k_count(const int* __restrict__ dst, int e) {
    int i = blockIdx.x * blockDim.x + threadIdx.x;
    if (i < e) g_rank[i] = atomicAdd(&g_cnt[dst[i]], 1);
}

// ---------------- scan1: block-local exclusive prefix of counts; + dinv ----------------
__global__ void k_scan1(int n) {
    __shared__ int sh[256];
    int t = threadIdx.x;
    int i = blockIdx.x * 256 + t;
    int v = (i < n) ? g_cnt[i] : 0;
    sh[t] = v;
    for (int off = 1; off < 256; off <<= 1) {
        __syncthreads();
        int x = (t >= off) ? sh[t - off] : 0;
        __syncthreads();
        sh[t] += x;
    }
    __syncthreads();
    if (i < n) {
        g_offs[i] = sh[t] - v;
        g_dinv[i] = rsqrtf((float)v + 1.0f);
    }
    if (t == 255) g_part[blockIdx.x] = sh[255];
}

// ---------------- scan2: exclusive prefix of block sums ----------------
__global__ void k_scan2(int nb) {
    __shared__ int sh[256];
    int t = threadIdx.x;
    int v = (t < nb) ? g_part[t] : 0;
    sh[t] = v;
    for (int off = 1; off < 256; off <<= 1) {
        __syncthreads();
        int x = (t >= off) ? sh[t - off] : 0;
        __syncthreads();
        sh[t] += x;
    }
    __syncthreads();
    g_part2[t] = sh[t] - v;
}

// ---------------- fused: CSR fill (blocks < nbE) + GEMM1 HMMA (rest) ----------------
__global__ void k_big(const int* __restrict__ src, const int* __restrict__ dst, int e,
                      const float* __restrict__ x, const float* __restrict__ W1,
                      int n, int nbE) {
    __shared__ __align__(16) __half As[64 * 136];   // [row][k] pitch 136 halves
    __shared__ __align__(16) __half Bs[128 * 72];   // [k][c]  pitch 72 halves
    int t = threadIdx.x;

    if (blockIdx.x < nbE) {
        int i = blockIdx.x * 256 + t;
        if (i < e) {
            int d = dst[i];
            int p = g_offs[d] + g_part2[d >> 8] + g_rank[i];
            g_csr[p] = src[i];
        }
        return;
    }

    int gb = blockIdx.x - nbE;
    int row0 = gb * 64;
    int lane = t & 31, w = t >> 5;
    int wm = w & 3, wn = w >> 2;

    int ngb = gridDim.x - nbE;
    for (int i = gb * 256 + t; i < n; i += ngb * 256) g_cnt[i] = 0;

    for (int i = t; i < 64 * 32; i += 256) {
        int r = i >> 5, c4 = i & 31;
        int gr = row0 + r; if (gr >= n) gr = row0;
        float4 v = *(const float4*)&x[gr * DIN + c4 * 4];
        *(__half2*)&As[r * 136 + c4 * 4]     = __floats2half2_rn(v.x, v.y);
        *(__half2*)&As[r * 136 + c4 * 4 + 2] = __floats2half2_rn(v.z, v.w);
    }
    for (int i = t; i < 128 * 16; i += 256) {
        int k = i >> 4, c4 = i & 15;
        float4 v = *(const float4*)&W1[k * DHID + c4 * 4];
        *(__half2*)&Bs[k * 72 + c4 * 4]     = __floats2half2_rn(v.x, v.y);
        *(__half2*)&Bs[k * 72 + c4 * 4 + 2] = __floats2half2_rn(v.z, v.w);
    }
    __syncthreads();

    float acc[4][4];
#pragma unroll
    for (int nf = 0; nf < 4; nf++)
#pragma unroll
        for (int r = 0; r < 4; r++) acc[nf][r] = 0.f;

    int arow = wm * 16 + (lane & 15);
    int acol8 = (lane >> 4) * 8;
#pragma unroll
    for (int ks = 0; ks < 8; ks++) {
        int k0 = ks * 16;
        uint32_t a0, a1, a2, a3;
        LDMATRIX_X4(a0, a1, a2, a3, smem_u32(&As[arow * 136 + k0 + acol8]));
#pragma unroll
        for (int nf = 0; nf < 4; nf++) {
            uint32_t b0, b1;
            LDMATRIX_X2T(b0, b1, smem_u32(&Bs[(k0 + (lane & 15)) * 72 + wn * 32 + nf * 8]));
            MMA16816(acc[nf][0], acc[nf][1], acc[nf][2], acc[nf][3], a0, a1, a2, a3, b0, b1);
        }
    }

    int g = lane >> 2, tig = lane & 3;
#pragma unroll
    for (int half = 0; half < 2; half++) {
        int gr = row0 + wm * 16 + g + half * 8;
        if (gr < n) {
            float di = g_dinv[gr];
#pragma unroll
            for (int nf = 0; nf < 4; nf++) {
                float c0 = acc[nf][half * 2] * di;
                float c1 = acc[nf][half * 2 + 1] * di;
                g_hs[gr * 32 + wn * 16 + nf * 4 + tig] = __floats2half2_rn(c0, c1);
            }
        }
    }
}

__device__ __forceinline__ int offs_beg(int v)        { return g_offs[v] + g_part2[v >> 8]; }
__device__ __forceinline__ int offs_end(int v, int n, int e) {
    return (v + 1 < n) ? g_offs[v + 1] + g_part2[(v + 1) >> 8] : e;
}

// unpack uint2 (4 halves) and accumulate into float4
__device__ __forceinline__ void acc_u2(float4& a, uint2 v) {
    __half2 h0 = *reinterpret_cast<__half2*>(&v.x);
    __half2 h1 = *reinterpret_cast<__half2*>(&v.y);
    float2 f0 = __half22float2(h0), f1 = __half22float2(h1);
    a.x += f0.x; a.y += f0.y; a.z += f1.x; a.w += f1.y;
}

// ---------------- gather (dual-neighbor): warp = 1 node, half-warps process 2 neighbors ----------------
// lanes 0-15 -> even neighbor, lanes 16-31 -> odd neighbor, each lane owns 8B (4 halves).
template<int PHASE>
__device__ __forceinline__ void gather_body(const float* __restrict__ b1, int n, int e) {
    int gt   = blockIdx.x * blockDim.x + threadIdx.x;
    int node = gt >> 5;
    int lane = gt & 31;
    if (node >= n) return;
    int half = lane >> 4;          // 0 or 1
    int lc   = lane & 15;          // 8B chunk index within the 128B row
    const __half2* __restrict__ feat = PHASE ? g_zs : g_hs;

    float4 acc = make_float4(0.f, 0.f, 0.f, 0.f);
    // self-loop: half 0 only
    if (half == 0)
        acc_u2(acc, ((const uint2*)(feat + node * 32))[lc]);

    int beg = offs_beg(node), end = offs_end(node, n, e);
    int j = beg;
    for (; j + 4 <= end; j += 4) {
        int sA = g_csr[j + half];
        int sB = g_csr[j + 2 + half];
        uint2 vA = ((const uint2*)(feat + sA * 32))[lc];
        uint2 vB = ((const uint2*)(feat + sB * 32))[lc];
        acc_u2(acc, vA);
        acc_u2(acc, vB);
    }
    if (j + 2 <= end) {
        int s = g_csr[j + half];
        acc_u2(acc, ((const uint2*)(feat + s * 32))[lc]);
        j += 2;
    }
    if (j < end && half == 0) {    // odd remaining edge: half 0 takes it
        int s = g_csr[j];
        acc_u2(acc, ((const uint2*)(feat + s * 32))[lc]);
    }

    // combine the two half-warps
    acc.x += __shfl_xor_sync(0xffffffff, acc.x, 16);
    acc.y += __shfl_xor_sync(0xffffffff, acc.y, 16);
    acc.z += __shfl_xor_sync(0xffffffff, acc.z, 16);
    acc.w += __shfl_xor_sync(0xffffffff, acc.w, 16);

    if (half == 0) {
        float* aggout = PHASE ? g_agg2 : g_agg;
        *(float4*)&aggout[node * DHID + lc * 4] = acc;
        if (PHASE == 0) {
            // fused relu epilogue -> g_zs
            float di = g_dinv[node];
            float4 b = *(const float4*)&b1[lc * 4];
            float o0 = fmaxf(acc.x * di + b.x, 0.f) * di;
            float o1 = fmaxf(acc.y * di + b.y, 0.f) * di;
            float o2 = fmaxf(acc.z * di + b.z, 0.f) * di;
            float o3 = fmaxf(acc.w * di + b.w, 0.f) * di;
            __half2 h0 = __floats2half2_rn(o0, o1);
            __half2 h1 = __floats2half2_rn(o2, o3);
            uint2 pk;
            pk.x = *reinterpret_cast<uint32_t*>(&h0);
            pk.y = *reinterpret_cast<uint32_t*>(&h1);
            ((uint2*)(g_zs + node * 32))[lc] = pk;
        }
    }
}

__global__ void k_gather1(const float* __restrict__ b1, int n, int e) { gather_body<0>(b1, n, e); }
__global__ void k_gather2(int n, int e)                               { gather_body<1>(nullptr, n, e); }

// ---------------- final (HMMA): out = x + h1@Wl + a2@W2 + bl + b2 ----------------
__global__ void k_final(const float* __restrict__ x,  const float* __restrict__ Wl,
                        const float* __restrict__ W2, const float* __restrict__ b1,
                        const float* __restrict__ bl, const float* __restrict__ b2,
                        float* __restrict__ out, int n) {
    __shared__ __align__(16) __half As[32 * 72];     // [row][k] pitch 72 halves
    __shared__ __align__(16) __half Bs[64 * 136];    // [k][c]  pitch 136 halves
    int t = threadIdx.x;
    int lane = t & 31, w = t >> 5;
    int wm = w & 1, wn = w >> 1;
    int row0 = blockIdx.x * 32;

    float acc[4][4];
#pragma unroll
    for (int nf = 0; nf < 4; nf++)
#pragma unroll
        for (int r = 0; r < 4; r++) acc[nf][r] = 0.f;

    for (int phase = 0; phase < 2; phase++) {
        const float* A  = phase ? g_agg2 : g_agg;
        const float* Wg = phase ? W2 : Wl;
        __syncthreads();
        for (int i = t; i < 32 * 16; i += 256) {
            int r = i >> 4, c4 = i & 15;
            int gr = row0 + r; if (gr >= n) gr = row0;
            float di = g_dinv[gr];
            float4 v = *(const float4*)&A[gr * DHID + c4 * 4];
            v.x *= di; v.y *= di; v.z *= di; v.w *= di;
            if (phase == 0) {
                float4 b = *(const float4*)&b1[c4 * 4];
                v.x += b.x; v.y += b.y; v.z += b.z; v.w += b.w;
            }
            *(__half2*)&As[r * 72 + c4 * 4]     = __floats2half2_rn(v.x, v.y);
            *(__half2*)&As[r * 72 + c4 * 4 + 2] = __floats2half2_rn(v.z, v.w);
        }
        for (int i = t; i < 64 * 32; i += 256) {
            int k = i >> 5, c4 = i & 31;
            float4 v = *(const float4*)&Wg[k * DOUT + c4 * 4];
            *(__half2*)&Bs[k * 136 + c4 * 4]     = __floats2half2_rn(v.x, v.y);
            *(__half2*)&Bs[k * 136 + c4 * 4 + 2] = __floats2half2_rn(v.z, v.w);
        }
        __syncthreads();

        int arow = wm * 16 + (lane & 15);
        int acol8 = (lane >> 4) * 8;
#pragma unroll
        for (int ks = 0; ks < 4; ks++) {
            int k0 = ks * 16;
            uint32_t a0, a1, a2, a3;
            LDMATRIX_X4(a0, a1, a2, a3, smem_u32(&As[arow * 72 + k0 + acol8]));
#pragma unroll
            for (int nf = 0; nf < 4; nf++) {
                uint32_t b0, b1r;
                LDMATRIX_X2T(b0, b1r, smem_u32(&Bs[(k0 + (lane & 15)) * 136 + wn * 32 + nf * 8]));
                MMA16816(acc[nf][0], acc[nf][1], acc[nf][2], acc[nf][3], a0, a1, a2, a3, b0, b1r);
            }
        }
    }

    int g = lane >> 2, tig = lane & 3;
#pragma unroll
    for (int half = 0; half < 2; half++) {
        int gr = row0 + wm * 16 + g + half * 8;
        if (gr < n) {
#pragma unroll
            for (int nf = 0; nf < 4; nf++) {
                int nc = wn * 32 + nf * 8 + tig * 2;
                float2 xv  = *(const float2*)&x[gr * DOUT + nc];
                float2 blv = *(const float2*)&bl[nc];
                float2 b2v = *(const float2*)&b2[nc];
                float2 ov;
                ov.x = acc[nf][half * 2]     + xv.x + blv.x + b2v.x;
                ov.y = acc[nf][half * 2 + 1] + xv.y + blv.y + b2v.y;
                *(float2*)&out[gr * DOUT + nc] = ov;
            }
        }
    }
}

// ---------------- launch (7 kernels) ----------------
extern "C" void kernel_launch(void* const* d_in, const int* in_sizes, int n_in,
                              void* d_out, int out_size) {
    const float* x  = (const float*)d_in[0];
    const int*   ei = (const int*)d_in[1];          // int32 (JAX x64 disabled)
    const float* W1 = (const float*)d_in[2];
    const float* b1 = (const float*)d_in[3];
    const float* Wl = (const float*)d_in[4];
    const float* bl = (const float*)d_in[5];
    const float* W2 = (const float*)d_in[6];
    const float* b2 = (const float*)d_in[7];
    float*       out = (float*)d_out;

    int n = in_sizes[0] / DIN;        // 50000
    int e = in_sizes[1] / 2;          // 800000
    const int* src = ei;
    const int* dst = ei + e;

    int nbN = (n + 255) / 256;        // 196
    int nbE = (e + 255) / 256;        // 3125
    int nbG = (n + 63) / 64;          // 782

    k_count  <<<nbE, 256>>>(dst, e);                        // 0
    k_scan1  <<<nbN, 256>>>(n);                             // 1 (+dinv)
    k_scan2  <<<1,   256>>>(nbN);                           // 2
    k_big    <<<nbE + nbG, 256>>>(src, dst, e, x, W1, n, nbE); // 3 <- profiled
    k_gather1<<<(n * 32 + 255) / 256, 256>>>(b1, n, e);     // 4
    k_gather2<<<(n * 32 + 255) / 256, 256>>>(n, e);         // 5
    k_final  <<<(n + 31) / 32, 256>>>(x, Wl, W2, b1, bl, b2, out, n);  // 6
}

// round 14
// speedup vs baseline: 1.0826x; 1.0826x over previous
#include <cuda_runtime.h>
#include <cuda_fp16.h>
#include <cstdint>

#define NN   50000
#define EE   800000
#define DIN  128
#define DHID 64
#define DOUT 128

// ---------------- scratch (static device globals; no allocation) ----------------
__device__ __align__(16) float g_dinv[NN];
__device__ int   g_cnt[NN];      // zero at load; re-zeroed by fused gemm blocks each call
__device__ __align__(16) int g_rank[EE];  // per-edge rank within its dst bucket
__device__ int   g_offs[NN];     // block-local exclusive prefix (scan1)
__device__ int   g_part[256];
__device__ int   g_part2[256];   // per-256-block global offset (scan2)
__device__ int   g_csr[EE];
__device__ __align__(16) __half2 g_hs[NN * 32];      // fp16 conv1 pre-agg features
__device__ __align__(16) __half2 g_zs[NN * 32];      // fp16 conv2 pre-agg features
__device__ __align__(16) float   g_agg [NN * DHID];  // gather1 result (fp32)
__device__ __align__(16) float   g_agg2[NN * DHID];  // gather2 result (fp32)

__device__ __forceinline__ uint32_t smem_u32(const void* p) {
    return (uint32_t)__cvta_generic_to_shared(p);
}

#define LDMATRIX_X4(a0,a1,a2,a3,addr) \
    asm volatile("ldmatrix.sync.aligned.m8n8.x4.shared.b16 {%0,%1,%2,%3}, [%4];" \
        : "=r"(a0),"=r"(a1),"=r"(a2),"=r"(a3) : "r"(addr))
#define LDMATRIX_X2T(b0,b1,addr) \
    asm volatile("ldmatrix.sync.aligned.m8n8.x2.trans.shared.b16 {%0,%1}, [%2];" \
        : "=r"(b0),"=r"(b1) : "r"(addr))
#define MMA16816(d0,d1,d2,d3,a0,a1,a2,a3,b0,b1) \
    asm volatile("mma.sync.aligned.m16n8k16.row.col.f32.f16.f16.f32 " \
        "{%0,%1,%2,%3},{%4,%5,%6,%7},{%8,%9},{%0,%1,%2,%3};" \
        : "+f"(d0),"+f"(d1),"+f"(d2),"+f"(d3) \
        : "r"(a0),"r"(a1),"r"(a2),"r"(a3),"r"(b0),"r"(b1))

// ---------------- count: degree histogram + per-edge rank (x4 vectorized) ----------------
__global__ void k_count(const int* __restrict__ dst, int e4) {
    int i = blockIdx.x * blockDim.x + threadIdx.x;   // int4 index
    if (i < e4) {
        int4 d = ((const int4*)dst)[i];
        int4 r;
        r.x = atomicAdd(&g_cnt[d.x], 1);
        r.y = atomicAdd(&g_cnt[d.y], 1);
        r.z = atomicAdd(&g_cnt[d.z], 1);
        r.w = atomicAdd(&g_cnt[d.w], 1);
        ((int4*)g_rank)[i] = r;
    }
}

// ---------------- scan1: block-local exclusive prefix of counts; + dinv ----------------
__global__ void k_scan1(int n) {
    __shared__ int sh[256];
    int t = threadIdx.x;
    int i = blockIdx.x * 256 + t;
    int v = (i < n) ? g_cnt[i] : 0;
    sh[t] = v;
    for (int off = 1; off < 256; off <<= 1) {
        __syncthreads();
        int x = (t >= off) ? sh[t - off] : 0;
        __syncthreads();
        sh[t] += x;
    }
    __syncthreads();
    if (i < n) {
        g_offs[i] = sh[t] - v;
        g_dinv[i] = rsqrtf((float)v + 1.0f);
    }
    if (t == 255) g_part[blockIdx.x] = sh[255];
}

// ---------------- scan2: exclusive prefix of block sums ----------------
__global__ void k_scan2(int nb) {
    __shared__ int sh[256];
    int t = threadIdx.x;
    int v = (t < nb) ? g_part[t] : 0;
    sh[t] = v;
    for (int off = 1; off < 256; off <<= 1) {
        __syncthreads();
        int x = (t >= off) ? sh[t - off] : 0;
        __syncthreads();
        sh[t] += x;
    }
    __syncthreads();
    g_part2[t] = sh[t] - v;
}

// ---------------- fused: CSR fill x4 (blocks < nbE4) + GEMM1 HMMA (rest) ----------------
__global__ void k_big(const int* __restrict__ src, const int* __restrict__ dst, int e4,
                      const float* __restrict__ x, const float* __restrict__ W1,
                      int n, int nbE4) {
    __shared__ __align__(16) __half As[64 * 136];   // [row][k] pitch 136 halves
    __shared__ __align__(16) __half Bs[128 * 72];   // [k][c]  pitch 72 halves
    int t = threadIdx.x;

    if (blockIdx.x < nbE4) {
        int i = blockIdx.x * 256 + t;               // int4 index
        if (i < e4) {
            int4 d = ((const int4*)dst)[i];
            int4 s = ((const int4*)src)[i];
            int4 r = ((const int4*)g_rank)[i];
            g_csr[g_offs[d.x] + g_part2[d.x >> 8] + r.x] = s.x;
            g_csr[g_offs[d.y] + g_part2[d.y >> 8] + r.y] = s.y;
            g_csr[g_offs[d.z] + g_part2[d.z >> 8] + r.z] = s.z;
            g_csr[g_offs[d.w] + g_part2[d.w >> 8] + r.w] = s.w;
        }
        return;
    }

    int gb = blockIdx.x - nbE4;
    int row0 = gb * 64;
    int lane = t & 31, w = t >> 5;
    int wm = w & 3, wn = w >> 2;

    int ngb = gridDim.x - nbE4;
    for (int i = gb * 256 + t; i < n; i += ngb * 256) g_cnt[i] = 0;

    for (int i = t; i < 64 * 32; i += 256) {
        int r = i >> 5, c4 = i & 31;
        int gr = row0 + r; if (gr >= n) gr = row0;
        float4 v = *(const float4*)&x[gr * DIN + c4 * 4];
        *(__half2*)&As[r * 136 + c4 * 4]     = __floats2half2_rn(v.x, v.y);
        *(__half2*)&As[r * 136 + c4 * 4 + 2] = __floats2half2_rn(v.z, v.w);
    }
    for (int i = t; i < 128 * 16; i += 256) {
        int k = i >> 4, c4 = i & 15;
        float4 v = *(const float4*)&W1[k * DHID + c4 * 4];
        *(__half2*)&Bs[k * 72 + c4 * 4]     = __floats2half2_rn(v.x, v.y);
        *(__half2*)&Bs[k * 72 + c4 * 4 + 2] = __floats2half2_rn(v.z, v.w);
    }
    __syncthreads();

    float acc[4][4];
#pragma unroll
    for (int nf = 0; nf < 4; nf++)
#pragma unroll
        for (int r = 0; r < 4; r++) acc[nf][r] = 0.f;

    int arow = wm * 16 + (lane & 15);
    int acol8 = (lane >> 4) * 8;
#pragma unroll
    for (int ks = 0; ks < 8; ks++) {
        int k0 = ks * 16;
        uint32_t a0, a1, a2, a3;
        LDMATRIX_X4(a0, a1, a2, a3, smem_u32(&As[arow * 136 + k0 + acol8]));
#pragma unroll
        for (int nf = 0; nf < 4; nf++) {
            uint32_t b0, b1;
            LDMATRIX_X2T(b0, b1, smem_u32(&Bs[(k0 + (lane & 15)) * 72 + wn * 32 + nf * 8]));
            MMA16816(acc[nf][0], acc[nf][1], acc[nf][2], acc[nf][3], a0, a1, a2, a3, b0, b1);
        }
    }

    int g = lane >> 2, tig = lane & 3;
#pragma unroll
    for (int half = 0; half < 2; half++) {
        int gr = row0 + wm * 16 + g + half * 8;
        if (gr < n) {
            float di = g_dinv[gr];
#pragma unroll
            for (int nf = 0; nf < 4; nf++) {
                float c0 = acc[nf][half * 2] * di;
                float c1 = acc[nf][half * 2 + 1] * di;
                g_hs[gr * 32 + wn * 16 + nf * 4 + tig] = __floats2half2_rn(c0, c1);
            }
        }
    }
}

__device__ __forceinline__ int offs_beg(int v)        { return g_offs[v] + g_part2[v >> 8]; }
__device__ __forceinline__ int offs_end(int v, int n, int e) {
    return (v + 1 < n) ? g_offs[v + 1] + g_part2[(v + 1) >> 8] : e;
}

// ---------------- gather1 (R12-proven form): g_agg = self + neighbors; fused relu -> g_zs ----------------
__global__ void k_gather1(const float* __restrict__ b1, int n, int e) {
    int gt   = blockIdx.x * blockDim.x + threadIdx.x;
    int node = gt >> 5;
    int lane = gt & 31;
    if (node >= n) return;

    float2 acc = __half22float2(g_hs[node * 32 + lane]);
    int beg = offs_beg(node), end = offs_end(node, n, e);
    int j = beg;
    for (; j + 4 <= end; j += 4) {
        int s0 = g_csr[j], s1 = g_csr[j + 1], s2 = g_csr[j + 2], s3 = g_csr[j + 3];
        float2 v0 = __half22float2(g_hs[s0 * 32 + lane]);
        float2 v1 = __half22float2(g_hs[s1 * 32 + lane]);
        float2 v2 = __half22float2(g_hs[s2 * 32 + lane]);
        float2 v3 = __half22float2(g_hs[s3 * 32 + lane]);
        acc.x += v0.x + v1.x + v2.x + v3.x;
        acc.y += v0.y + v1.y + v2.y + v3.y;
    }
    for (; j < end; j++) {
        int s = g_csr[j];
        float2 v = __half22float2(g_hs[s * 32 + lane]);
        acc.x += v.x; acc.y += v.y;
    }
    ((float2*)g_agg)[node * 32 + lane] = acc;

    float di = g_dinv[node];
    float2 b = *(const float2*)&b1[lane * 2];
    float ox = fmaxf(acc.x * di + b.x, 0.f) * di;
    float oy = fmaxf(acc.y * di + b.y, 0.f) * di;
    g_zs[node * 32 + lane] = __floats2half2_rn(ox, oy);
}

// ---------------- gather2: g_agg2 = self + neighbors over g_zs ----------------
__global__ void k_gather2(int n, int e) {
    int gt   = blockIdx.x * blockDim.x + threadIdx.x;
    int node = gt >> 5;
    int lane = gt & 31;
    if (node >= n) return;

    float2 acc = __half22float2(g_zs[node * 32 + lane]);
    int beg = offs_beg(node), end = offs_end(node, n, e);
    int j = beg;
    for (; j + 4 <= end; j += 4) {
        int s0 = g_csr[j], s1 = g_csr[j + 1], s2 = g_csr[j + 2], s3 = g_csr[j + 3];
        float2 v0 = __half22float2(g_zs[s0 * 32 + lane]);
        float2 v1 = __half22float2(g_zs[s1 * 32 + lane]);
        float2 v2 = __half22float2(g_zs[s2 * 32 + lane]);
        float2 v3 = __half22float2(g_zs[s3 * 32 + lane]);
        acc.x += v0.x + v1.x + v2.x + v3.x;
        acc.y += v0.y + v1.y + v2.y + v3.y;
    }
    for (; j < end; j++) {
        int s = g_csr[j];
        float2 v = __half22float2(g_zs[s * 32 + lane]);
        acc.x += v.x; acc.y += v.y;
    }
    ((float2*)g_agg2)[node * 32 + lane] = acc;
}

// ---------------- final (HMMA): out = x + h1@Wl + a2@W2 + bl + b2 ----------------
__global__ void k_final(const float* __restrict__ x,  const float* __restrict__ Wl,
                        const float* __restrict__ W2, const float* __restrict__ b1,
                        const float* __restrict__ bl, const float* __restrict__ b2,
                        float* __restrict__ out, int n) {
    __shared__ __align__(16) __half As[32 * 72];     // [row][k] pitch 72 halves
    __shared__ __align__(16) __half Bs[64 * 136];    // [k][c]  pitch 136 halves
    int t = threadIdx.x;
    int lane = t & 31, w = t >> 5;
    int wm = w & 1, wn = w >> 1;
    int row0 = blockIdx.x * 32;

    float acc[4][4];
#pragma unroll
    for (int nf = 0; nf < 4; nf++)
#pragma unroll
        for (int r = 0; r < 4; r++) acc[nf][r] = 0.f;

    for (int phase = 0; phase < 2; phase++) {
        const float* A  = phase ? g_agg2 : g_agg;
        const float* Wg = phase ? W2 : Wl;
        __syncthreads();
        for (int i = t; i < 32 * 16; i += 256) {
            int r = i >> 4, c4 = i & 15;
            int gr = row0 + r; if (gr >= n) gr = row0;
            float di = g_dinv[gr];
            float4 v = *(const float4*)&A[gr * DHID + c4 * 4];
            v.x *= di; v.y *= di; v.z *= di; v.w *= di;
            if (phase == 0) {
                float4 b = *(const float4*)&b1[c4 * 4];
                v.x += b.x; v.y += b.y; v.z += b.z; v.w += b.w;
            }
            *(__half2*)&As[r * 72 + c4 * 4]     = __floats2half2_rn(v.x, v.y);
            *(__half2*)&As[r * 72 + c4 * 4 + 2] = __floats2half2_rn(v.z, v.w);
        }
        for (int i = t; i < 64 * 32; i += 256) {
            int k = i >> 5, c4 = i & 31;
            float4 v = *(const float4*)&Wg[k * DOUT + c4 * 4];
            *(__half2*)&Bs[k * 136 + c4 * 4]     = __floats2half2_rn(v.x, v.y);
            *(__half2*)&Bs[k * 136 + c4 * 4 + 2] = __floats2half2_rn(v.z, v.w);
        }
        __syncthreads();

        int arow = wm * 16 + (lane & 15);
        int acol8 = (lane >> 4) * 8;
#pragma unroll
        for (int ks = 0; ks < 4; ks++) {
            int k0 = ks * 16;
            uint32_t a0, a1, a2, a3;
            LDMATRIX_X4(a0, a1, a2, a3, smem_u32(&As[arow * 72 + k0 + acol8]));
#pragma unroll
            for (int nf = 0; nf < 4; nf++) {
                uint32_t b0, b1r;
                LDMATRIX_X2T(b0, b1r, smem_u32(&Bs[(k0 + (lane & 15)) * 136 + wn * 32 + nf * 8]));
                MMA16816(acc[nf][0], acc[nf][1], acc[nf][2], acc[nf][3], a0, a1, a2, a3, b0, b1r);
            }
        }
    }

    int g = lane >> 2, tig = lane & 3;
#pragma unroll
    for (int half = 0; half < 2; half++) {
        int gr = row0 + wm * 16 + g + half * 8;
        if (gr < n) {
#pragma unroll
            for (int nf = 0; nf < 4; nf++) {
                int nc = wn * 32 + nf * 8 + tig * 2;
                float2 xv  = *(const float2*)&x[gr * DOUT + nc];
                float2 blv = *(const float2*)&bl[nc];
                float2 b2v = *(const float2*)&b2[nc];
                float2 ov;
                ov.x = acc[nf][half * 2]     + xv.x + blv.x + b2v.x;
                ov.y = acc[nf][half * 2 + 1] + xv.y + blv.y + b2v.y;
                *(float2*)&out[gr * DOUT + nc] = ov;
            }
        }
    }
}

// ---------------- launch (7 kernels) ----------------
extern "C" void kernel_launch(void* const* d_in, const int* in_sizes, int n_in,
                              void* d_out, int out_size) {
    const float* x  = (const float*)d_in[0];
    const int*   ei = (const int*)d_in[1];          // int32 (JAX x64 disabled)
    const float* W1 = (const float*)d_in[2];
    const float* b1 = (const float*)d_in[3];
    const float* Wl = (const float*)d_in[4];
    const float* bl = (const float*)d_in[5];
    const float* W2 = (const float*)d_in[6];
    const float* b2 = (const float*)d_in[7];
    float*       out = (float*)d_out;

    int n = in_sizes[0] / DIN;        // 50000
    int e = in_sizes[1] / 2;          // 800000
    int e4 = e / 4;                   // 200000 (e divisible by 4)
    const int* src = ei;
    const int* dst = ei + e;

    int nbN  = (n + 255) / 256;       // 196
    int nbE4 = (e4 + 255) / 256;      // 782
    int nbG  = (n + 63) / 64;         // 782

    k_count  <<<nbE4, 256>>>(dst, e4);                      // 0
    k_scan1  <<<nbN, 256>>>(n);                             // 1 (+dinv)
    k_scan2  <<<1,   256>>>(nbN);                           // 2
    k_big    <<<nbE4 + nbG, 256>>>(src, dst, e4, x, W1, n, nbE4); // 3 <- profiled
    k_gather1<<<(n * 32 + 255) / 256, 256>>>(b1, n, e);     // 4
    k_gather2<<<(n * 32 + 255) / 256, 256>>>(n, e);         // 5
    k_final  <<<(n + 31) / 32, 256>>>(x, Wl, W2, b1, bl, b2, out, n);  // 6
}

// round 16
// speedup vs baseline: 1.1298x; 1.0436x over previous
#include <cuda_runtime.h>
#include <cuda_fp16.h>
#include <cstdint>

#define NN   50000
#define EE   800000
#define DIN  128
#define DHID 64
#define DOUT 128

// ---------------- scratch (static device globals; no allocation) ----------------
__device__ __align__(16) float g_dinv[NN];
__device__ int   g_cnt[NN];      // zero at load; re-zeroed by fused gemm blocks each call
__device__ __align__(16) int g_rank[EE];  // per-edge rank within its dst bucket
__device__ int   g_offs[NN];     // block-local exclusive prefix (scan1)
__device__ int   g_part[256];
__device__ int   g_part2[256];   // per-256-block global offset (scan2)
__device__ int   g_csr[EE];
__device__ __align__(16) __half2 g_hs[NN * 32];   // fp16 conv1 pre-agg features
__device__ __align__(16) __half2 g_zs[NN * 32];   // fp16 conv2 pre-agg features
__device__ __align__(16) __half2 g_h1[NN * 32];   // fp16 h1 = agg1*dinv + b1 (final phase-0 A)

__device__ __forceinline__ uint32_t smem_u32(const void* p) {
    return (uint32_t)__cvta_generic_to_shared(p);
}

#define LDMATRIX_X4(a0,a1,a2,a3,addr) \
    asm volatile("ldmatrix.sync.aligned.m8n8.x4.shared.b16 {%0,%1,%2,%3}, [%4];" \
        : "=r"(a0),"=r"(a1),"=r"(a2),"=r"(a3) : "r"(addr))
#define LDMATRIX_X2T(b0,b1,addr) \
    asm volatile("ldmatrix.sync.aligned.m8n8.x2.trans.shared.b16 {%0,%1}, [%2];" \
        : "=r"(b0),"=r"(b1) : "r"(addr))
#define MMA16816(d0,d1,d2,d3,a0,a1,a2,a3,b0,b1) \
    asm volatile("mma.sync.aligned.m16n8k16.row.col.f32.f16.f16.f32 " \
        "{%0,%1,%2,%3},{%4,%5,%6,%7},{%8,%9},{%0,%1,%2,%3};" \
        : "+f"(d0),"+f"(d1),"+f"(d2),"+f"(d3) \
        : "r"(a0),"r"(a1),"r"(a2),"r"(a3),"r"(b0),"r"(b1))

// ---------------- count: degree histogram + per-edge rank (x4) ----------------
__global__ void k_count(const int* __restrict__ dst, int e4) {
    int i = blockIdx.x * blockDim.x + threadIdx.x;
    if (i < e4) {
        int4 d = ((const int4*)dst)[i];
        int4 r;
        r.x = atomicAdd(&g_cnt[d.x], 1);
        r.y = atomicAdd(&g_cnt[d.y], 1);
        r.z = atomicAdd(&g_cnt[d.z], 1);
        r.w = atomicAdd(&g_cnt[d.w], 1);
        ((int4*)g_rank)[i] = r;
    }
}

// ---------------- scan1: block-local exclusive prefix; + dinv ----------------
__global__ void k_scan1(int n) {
    __shared__ int sh[256];
    int t = threadIdx.x;
    int i = blockIdx.x * 256 + t;
    int v = (i < n) ? g_cnt[i] : 0;
    sh[t] = v;
    for (int off = 1; off < 256; off <<= 1) {
        __syncthreads();
        int x = (t >= off) ? sh[t - off] : 0;
        __syncthreads();
        sh[t] += x;
    }
    __syncthreads();
    if (i < n) {
        g_offs[i] = sh[t] - v;
        g_dinv[i] = rsqrtf((float)v + 1.0f);
    }
    if (t == 255) g_part[blockIdx.x] = sh[255];
}

// ---------------- scan2: exclusive prefix of block sums ----------------
__global__ void k_scan2(int nb) {
    __shared__ int sh[256];
    int t = threadIdx.x;
    int v = (t < nb) ? g_part[t] : 0;
    sh[t] = v;
    for (int off = 1; off < 256; off <<= 1) {
        __syncthreads();
        int x = (t >= off) ? sh[t - off] : 0;
        __syncthreads();
        sh[t] += x;
    }
    __syncthreads();
    g_part2[t] = sh[t] - v;
}

// ---------------- fused: CSR fill x4 (blocks < nbE4) + GEMM1 HMMA (rest) ----------------
__global__ void k_big(const int* __restrict__ src, const int* __restrict__ dst, int e4,
                      const float* __restrict__ x, const float* __restrict__ W1,
                      int n, int nbE4) {
    __shared__ __align__(16) __half As[64 * 136];
    __shared__ __align__(16) __half Bs[128 * 72];
    int t = threadIdx.x;

    if (blockIdx.x < nbE4) {
        int i = blockIdx.x * 256 + t;
        if (i < e4) {
            int4 d = ((const int4*)dst)[i];
            int4 s = ((const int4*)src)[i];
            int4 r = ((const int4*)g_rank)[i];
            g_csr[g_offs[d.x] + g_part2[d.x >> 8] + r.x] = s.x;
            g_csr[g_offs[d.y] + g_part2[d.y >> 8] + r.y] = s.y;
            g_csr[g_offs[d.z] + g_part2[d.z >> 8] + r.z] = s.z;
            g_csr[g_offs[d.w] + g_part2[d.w >> 8] + r.w] = s.w;
        }
        return;
    }

    int gb = blockIdx.x - nbE4;
    int row0 = gb * 64;
    int lane = t & 31, w = t >> 5;
    int wm = w & 3, wn = w >> 2;

    int ngb = gridDim.x - nbE4;
    for (int i = gb * 256 + t; i < n; i += ngb * 256) g_cnt[i] = 0;

    for (int i = t; i < 64 * 32; i += 256) {
        int r = i >> 5, c4 = i & 31;
        int gr = row0 + r; if (gr >= n) gr = row0;
        float4 v = *(const float4*)&x[gr * DIN + c4 * 4];
        *(__half2*)&As[r * 136 + c4 * 4]     = __floats2half2_rn(v.x, v.y);
        *(__half2*)&As[r * 136 + c4 * 4 + 2] = __floats2half2_rn(v.z, v.w);
    }
    for (int i = t; i < 128 * 16; i += 256) {
        int k = i >> 4, c4 = i & 15;
        float4 v = *(const float4*)&W1[k * DHID + c4 * 4];
        *(__half2*)&Bs[k * 72 + c4 * 4]     = __floats2half2_rn(v.x, v.y);
        *(__half2*)&Bs[k * 72 + c4 * 4 + 2] = __floats2half2_rn(v.z, v.w);
    }
    __syncthreads();

    float acc[4][4];
#pragma unroll
    for (int nf = 0; nf < 4; nf++)
#pragma unroll
        for (int r = 0; r < 4; r++) acc[nf][r] = 0.f;

    int arow = wm * 16 + (lane & 15);
    int acol8 = (lane >> 4) * 8;
#pragma unroll
    for (int ks = 0; ks < 8; ks++) {
        int k0 = ks * 16;
        uint32_t a0, a1, a2, a3;
        LDMATRIX_X4(a0, a1, a2, a3, smem_u32(&As[arow * 136 + k0 + acol8]));
#pragma unroll
        for (int nf = 0; nf < 4; nf++) {
            uint32_t b0, b1;
            LDMATRIX_X2T(b0, b1, smem_u32(&Bs[(k0 + (lane & 15)) * 72 + wn * 32 + nf * 8]));
            MMA16816(acc[nf][0], acc[nf][1], acc[nf][2], acc[nf][3], a0, a1, a2, a3, b0, b1);
        }
    }

    int g = lane >> 2, tig = lane & 3;
#pragma unroll
    for (int half = 0; half < 2; half++) {
        int gr = row0 + wm * 16 + g + half * 8;
        if (gr < n) {
            float di = g_dinv[gr];
#pragma unroll
            for (int nf = 0; nf < 4; nf++) {
                float c0 = acc[nf][half * 2] * di;
                float c1 = acc[nf][half * 2 + 1] * di;
                g_hs[gr * 32 + wn * 16 + nf * 4 + tig] = __floats2half2_rn(c0, c1);
            }
        }
    }
}

__device__ __forceinline__ int offs_beg(int v)        { return g_offs[v] + g_part2[v >> 8]; }
__device__ __forceinline__ int offs_end(int v, int n, int e) {
    return (v + 1 < n) ? g_offs[v + 1] + g_part2[(v + 1) >> 8] : e;
}

// ---------------- gather1: fp32 acc over g_hs; write h1 (fp16) + zs (fp16) ----------------
__global__ void k_gather1(const float* __restrict__ b1, int n, int e) {
    int gt   = blockIdx.x * blockDim.x + threadIdx.x;
    int node = gt >> 5;
    int lane = gt & 31;
    if (node >= n) return;

    float2 acc = __half22float2(g_hs[node * 32 + lane]);
    int beg = offs_beg(node), end = offs_end(node, n, e);
    int j = beg;
    for (; j + 4 <= end; j += 4) {
        int s0 = g_csr[j], s1 = g_csr[j + 1], s2 = g_csr[j + 2], s3 = g_csr[j + 3];
        float2 v0 = __half22float2(g_hs[s0 * 32 + lane]);
        float2 v1 = __half22float2(g_hs[s1 * 32 + lane]);
        float2 v2 = __half22float2(g_hs[s2 * 32 + lane]);
        float2 v3 = __half22float2(g_hs[s3 * 32 + lane]);
        acc.x += v0.x + v1.x + v2.x + v3.x;
        acc.y += v0.y + v1.y + v2.y + v3.y;
    }
    for (; j < end; j++) {
        int s = g_csr[j];
        float2 v = __half22float2(g_hs[s * 32 + lane]);
        acc.x += v.x; acc.y += v.y;
    }

    float di = g_dinv[node];
    float2 b = *(const float2*)&b1[lane * 2];
    float h1x = acc.x * di + b.x;
    float h1y = acc.y * di + b.y;
    g_h1[node * 32 + lane] = __floats2half2_rn(h1x, h1y);
    g_zs[node * 32 + lane] = __floats2half2_rn(fmaxf(h1x, 0.f) * di, fmaxf(h1y, 0.f) * di);
}

// ---------------- final (fused gather2 + dual HMMA): out = x + h1@Wl + a2@W2 + bl + b2 ----------------
// 32-row tile, 8 warps (2m x 4n). Each warp gathers 4 rows of the phase-1 A tile from g_zs.
__global__ void k_final(const float* __restrict__ x,  const float* __restrict__ Wl,
                        const float* __restrict__ W2,
                        const float* __restrict__ bl, const float* __restrict__ b2,
                        float* __restrict__ out, int n, int e) {
    __shared__ __align__(16) __half As0[32 * 72];    // phase-0 A (h1, fp16 copy)
    __shared__ __align__(16) __half As1[32 * 72];    // phase-1 A (gathered a2*dinv)
    __shared__ __align__(16) __half Bs[64 * 136];    // weights
    int t = threadIdx.x;
    int lane = t & 31, w = t >> 5;
    int wm = w & 1, wn = w >> 1;
    int row0 = blockIdx.x * 32;

    // (a) gather conv2 rows into As1: warp w handles rows w, w+8, w+16, w+24
    for (int rr = w; rr < 32; rr += 8) {
        int node = row0 + rr;
        int nd = (node < n) ? node : row0;
        float2 acc = __half22float2(g_zs[nd * 32 + lane]);   // self-loop
        int beg = offs_beg(nd), end = offs_end(nd, n, e);
        int j = beg;
        for (; j + 4 <= end; j += 4) {
            int s0 = g_csr[j], s1 = g_csr[j + 1], s2 = g_csr[j + 2], s3 = g_csr[j + 3];
            float2 v0 = __half22float2(g_zs[s0 * 32 + lane]);
            float2 v1 = __half22float2(g_zs[s1 * 32 + lane]);
            float2 v2 = __half22float2(g_zs[s2 * 32 + lane]);
            float2 v3 = __half22float2(g_zs[s3 * 32 + lane]);
            acc.x += v0.x + v1.x + v2.x + v3.x;
            acc.y += v0.y + v1.y + v2.y + v3.y;
        }
        for (; j < end; j++) {
            int s = g_csr[j];
            float2 v = __half22float2(g_zs[s * 32 + lane]);
            acc.x += v.x; acc.y += v.y;
        }
        float di = g_dinv[nd];
        *(__half2*)&As1[rr * 72 + lane * 2] = __floats2half2_rn(acc.x * di, acc.y * di);
    }

    // (b) phase-0 A tile: direct fp16 copy of g_h1 rows (16B chunks)
    for (int i = t; i < 32 * 8; i += 256) {
        int r = i >> 3, c = i & 7;
        int gr = row0 + r; if (gr >= n) gr = row0;
        *(uint4*)&As0[r * 72 + c * 8] = ((const uint4*)(g_h1 + gr * 32))[c];
    }
    // Bs = Wl
    for (int i = t; i < 64 * 32; i += 256) {
        int k = i >> 5, c4 = i & 31;
        float4 v = *(const float4*)&Wl[k * DOUT + c4 * 4];
        *(__half2*)&Bs[k * 136 + c4 * 4]     = __floats2half2_rn(v.x, v.y);
        *(__half2*)&Bs[k * 136 + c4 * 4 + 2] = __floats2half2_rn(v.z, v.w);
    }
    __syncthreads();

    float acc[4][4];
#pragma unroll
    for (int nf = 0; nf < 4; nf++)
#pragma unroll
        for (int r = 0; r < 4; r++) acc[nf][r] = 0.f;

    int arow = wm * 16 + (lane & 15);
    int acol8 = (lane >> 4) * 8;
#pragma unroll
    for (int ks = 0; ks < 4; ks++) {
        int k0 = ks * 16;
        uint32_t a0, a1, a2, a3;
        LDMATRIX_X4(a0, a1, a2, a3, smem_u32(&As0[arow * 72 + k0 + acol8]));
#pragma unroll
        for (int nf = 0; nf < 4; nf++) {
            uint32_t b0, b1r;
            LDMATRIX_X2T(b0, b1r, smem_u32(&Bs[(k0 + (lane & 15)) * 136 + wn * 32 + nf * 8]));
            MMA16816(acc[nf][0], acc[nf][1], acc[nf][2], acc[nf][3], a0, a1, a2, a3, b0, b1r);
        }
    }
    __syncthreads();
    // Bs = W2
    for (int i = t; i < 64 * 32; i += 256) {
        int k = i >> 5, c4 = i & 31;
        float4 v = *(const float4*)&W2[k * DOUT + c4 * 4];
        *(__half2*)&Bs[k * 136 + c4 * 4]     = __floats2half2_rn(v.x, v.y);
        *(__half2*)&Bs[k * 136 + c4 * 4 + 2] = __floats2half2_rn(v.z, v.w);
    }
    __syncthreads();
#pragma unroll
    for (int ks = 0; ks < 4; ks++) {
        int k0 = ks * 16;
        uint32_t a0, a1, a2, a3;
        LDMATRIX_X4(a0, a1, a2, a3, smem_u32(&As1[arow * 72 + k0 + acol8]));
#pragma unroll
        for (int nf = 0; nf < 4; nf++) {
            uint32_t b0, b1r;
            LDMATRIX_X2T(b0, b1r, smem_u32(&Bs[(k0 + (lane & 15)) * 136 + wn * 32 + nf * 8]));
            MMA16816(acc[nf][0], acc[nf][1], acc[nf][2], acc[nf][3], a0, a1, a2, a3, b0, b1r);
        }
    }

    int g = lane >> 2, tig = lane & 3;
#pragma unroll
    for (int half = 0; half < 2; half++) {
        int gr = row0 + wm * 16 + g + half * 8;
        if (gr < n) {
#pragma unroll
            for (int nf = 0; nf < 4; nf++) {
                int nc = wn * 32 + nf * 8 + tig * 2;
                float2 xv  = *(const float2*)&x[gr * DOUT + nc];
                float2 blv = *(const float2*)&bl[nc];
                float2 b2v = *(const float2*)&b2[nc];
                float2 ov;
                ov.x = acc[nf][half * 2]     + xv.x + blv.x + b2v.x;
                ov.y = acc[nf][half * 2 + 1] + xv.y + blv.y + b2v.y;
                *(float2*)&out[gr * DOUT + nc] = ov;
            }
        }
    }
}

// ---------------- launch (6 kernels) ----------------
extern "C" void kernel_launch(void* const* d_in, const int* in_sizes, int n_in,
                              void* d_out, int out_size) {
    const float* x  = (const float*)d_in[0];
    const int*   ei = (const int*)d_in[1];          // int32 (JAX x64 disabled)
    const float* W1 = (const float*)d_in[2];
    const float* b1 = (const float*)d_in[3];
    const float* Wl = (const float*)d_in[4];
    const float* bl = (const float*)d_in[5];
    const float* W2 = (const float*)d_in[6];
    const float* b2 = (const float*)d_in[7];
    float*       out = (float*)d_out;

    int n = in_sizes[0] / DIN;        // 50000
    int e = in_sizes[1] / 2;          // 800000
    int e4 = e / 4;
    const int* src = ei;
    const int* dst = ei + e;

    int nbN  = (n + 255) / 256;       // 196
    int nbE4 = (e4 + 255) / 256;      // 782
    int nbG  = (n + 63) / 64;         // 782

    k_count  <<<nbE4, 256>>>(dst, e4);                      // 0
    k_scan1  <<<nbN, 256>>>(n);                             // 1 (+dinv)
    k_scan2  <<<1,   256>>>(nbN);                           // 2
    k_big    <<<nbE4 + nbG, 256>>>(src, dst, e4, x, W1, n, nbE4); // 3 <- profiled
    k_gather1<<<(n * 32 + 255) / 256, 256>>>(b1, n, e);     // 4
    k_final  <<<(n + 31) / 32, 256>>>(x, Wl, W2, bl, b2, out, n, e); // 5
}